// round 10
// baseline (speedup 1.0000x reference)
#include <cuda_runtime.h>
#include <cuda_pipeline_primitives.h>

// SSIM loss, fused single pass + fused finalize. B=64, H=W=384, WIN=7.
//
// R10: packed f32x2 arithmetic (PTX add/mul/fma.rn.f32x2). The 2 output
// columns per thread form the 2 lanes; all window stats, rings, and the emit
// rational are packed 64-bit values. Odd-offset taps via mov.b64 repacks
// (alu pipe, idle). Subtract = fma(b,-1,a) (bit-exact). cp.async double
// buffering, NBANDS=7 (448 CTAs ~ 1 wave @ 3 CTAs/SM) kept from R9.

#define BATCH    64
#define HH       384
#define WW       384
#define WIN      7
#define OH       378
#define OW       378
#define NBANDS   7
#define OROWS    54
#define INROWS   60
#define NTHREADS 192
#define ROWW     392
#define NF4      (WW / 4)
#define NCTAS    (NBANDS * BATCH)       // 448

typedef unsigned long long ull;

__device__ __forceinline__ ull f2pk(float lo, float hi) {
    ull r; asm("mov.b64 %0, {%1, %2};" : "=l"(r) : "f"(lo), "f"(hi)); return r;
}
__device__ __forceinline__ float2 f2up(ull a) {
    float lo, hi; asm("mov.b64 {%0, %1}, %2;" : "=f"(lo), "=f"(hi) : "l"(a));
    return make_float2(lo, hi);
}
__device__ __forceinline__ ull f2add(ull a, ull b) {
    ull r; asm("add.rn.f32x2 %0, %1, %2;" : "=l"(r) : "l"(a), "l"(b)); return r;
}
__device__ __forceinline__ ull f2mul(ull a, ull b) {
    ull r; asm("mul.rn.f32x2 %0, %1, %2;" : "=l"(r) : "l"(a), "l"(b)); return r;
}
__device__ __forceinline__ ull f2fma(ull a, ull b, ull c) {
    ull r; asm("fma.rn.f32x2 %0, %1, %2, %3;" : "=l"(r) : "l"(a), "l"(b), "l"(c)); return r;
}
// a - b, exact (single rounding; -1*b exact)
#define F2SUB(a, b) f2fma((b), kNeg1, (a))

__device__ float g_part[NCTAS];
__device__ unsigned int g_count;

__global__ __launch_bounds__(NTHREADS, 3) void ssim_main_kernel(
    const float* __restrict__ X, const float* __restrict__ Y,
    const float* __restrict__ data_range, float* __restrict__ out)
{
    __shared__ float xb[2][WIN][ROWW];
    __shared__ float yb[2][WIN][ROWW];
    __shared__ float warpsum[NTHREADS / 32];
    __shared__ double dsum[NTHREADS / 32];
    __shared__ int is_last;

    const int t    = threadIdx.x;
    const int band = blockIdx.x;
    const int b    = blockIdx.y;
    const int row0 = band * OROWS;
    const int c    = 2 * t;

    const float L    = data_range[b];
    const float C1s  = (0.49f * L) * (0.49f * L);    // C1 * 49^2
    const float C2s  = (1.47f * L) * (1.47f * L);    // C2 * 49^2
    const float cvh  = 0.5f * (49.0f / 48.0f);

    const ull kNeg1 = f2pk(-1.0f, -1.0f);
    const ull kC1   = f2pk(C1s, C1s);
    const ull kC2   = f2pk(C2s, C2s);
    const ull kCh   = f2pk(0.5f, 0.5f);
    const ull kCvh  = f2pk(cvh, cvh);
    const ull k49   = f2pk(49.0f, 49.0f);

    const float* __restrict__ Xb = X + (size_t)b * HH * WW;
    const float* __restrict__ Yb = Y + (size_t)b * HH * WW;

    // packed rings: 4 stats x 7 deep (lanes = 2 cols)
    ull ru[WIN], rv[WIN], ruu[WIN], rvv[WIN];
#pragma unroll
    for (int i = 0; i < WIN; i++) { ru[i]=0ull; rv[i]=0ull; ruu[i]=0ull; rvv[i]=0ull; }
    ull Wu=0ull, Wv=0ull, Wuu=0ull, Wvv=0ull;

    float acc = 0.f;
    float pn = 0.f, pd = 1.f;
    bool  have = false;

    auto stage = [&](int bi, int r0, int nrows) {
        const float* __restrict__ Xr = Xb + (size_t)(row0 + r0) * WW;
        const float* __restrict__ Yr = Yb + (size_t)(row0 + r0) * WW;
        const int total = nrows * NF4;
        for (int e = t; e < total; e += NTHREADS) {
            const int rr = e / NF4;
            const int cc = (e - rr * NF4) * 4;
            __pipeline_memcpy_async(&xb[bi][rr][cc], Xr + rr * WW + cc, 16);
            __pipeline_memcpy_async(&yb[bi][rr][cc], Yr + rr * WW + cc, 16);
        }
        __pipeline_commit();
    };

    auto dorow = [&](int bi, int i, bool emit) {
        // 8 LDS.64: natural even-offset pairs (c+0,c+1)..(c+6,c+7)
        const ull ax0 = *(const ull*)&xb[bi][i][c];
        const ull ax1 = *(const ull*)&xb[bi][i][c + 2];
        const ull ax2 = *(const ull*)&xb[bi][i][c + 4];
        const ull ax3 = *(const ull*)&xb[bi][i][c + 6];
        const ull ay0 = *(const ull*)&yb[bi][i][c];
        const ull ay1 = *(const ull*)&yb[bi][i][c + 2];
        const ull ay2 = *(const ull*)&yb[bi][i][c + 4];
        const ull ay3 = *(const ull*)&yb[bi][i][c + 6];

        // u = x+y, v = x-y (packed even pairs)
        const ull uE0 = f2add(ax0, ay0);
        const ull uE1 = f2add(ax1, ay1);
        const ull uE2 = f2add(ax2, ay2);
        const ull uE3 = f2add(ax3, ay3);
        const ull vE0 = F2SUB(ax0, ay0);
        const ull vE1 = F2SUB(ax1, ay1);
        const ull vE2 = F2SUB(ax2, ay2);
        const ull vE3 = F2SUB(ax3, ay3);

        // odd-offset taps via lane repack (alu movs)
        const float2 p0 = f2up(uE0), p1 = f2up(uE1), p2 = f2up(uE2), p3 = f2up(uE3);
        const ull uO0 = f2pk(p0.y, p1.x);
        const ull uO1 = f2pk(p1.y, p2.x);
        const ull uO2 = f2pk(p2.y, p3.x);
        const float2 q0 = f2up(vE0), q1 = f2up(vE1), q2 = f2up(vE2), q3 = f2up(vE3);
        const ull vO0 = f2pk(q0.y, q1.x);
        const ull vO1 = f2pk(q1.y, q2.x);
        const ull vO2 = f2pk(q2.y, q3.x);

        // 7-tap horizontal sums, both columns at once
        const ull su = f2add(f2add(f2add(uE0, uO0), f2add(uE1, uO1)),
                             f2add(f2add(uE2, uO2), uE3));
        const ull sv = f2add(f2add(f2add(vE0, vO0), f2add(vE1, vO1)),
                             f2add(f2add(vE2, vO2), vE3));
        ull suu = f2mul(uE0, uE0);
        suu = f2fma(uO0, uO0, suu); suu = f2fma(uE1, uE1, suu);
        suu = f2fma(uO1, uO1, suu); suu = f2fma(uE2, uE2, suu);
        suu = f2fma(uO2, uO2, suu); suu = f2fma(uE3, uE3, suu);
        ull svv = f2mul(vE0, vE0);
        svv = f2fma(vO0, vO0, svv); svv = f2fma(vE1, vE1, svv);
        svv = f2fma(vO1, vO1, svv); svv = f2fma(vE2, vE2, svv);
        svv = f2fma(vO2, vO2, svv); svv = f2fma(vE3, vE3, svv);

        // vertical running windows (packed rings)
        Wu  = f2add(Wu,  F2SUB(su,  ru[i]));  ru[i]  = su;
        Wv  = f2add(Wv,  F2SUB(sv,  rv[i]));  rv[i]  = sv;
        Wuu = f2add(Wuu, F2SUB(suu, ruu[i])); ruu[i] = suu;
        Wvv = f2add(Wvv, F2SUB(svv, rvv[i])); rvv[i] = svv;

        if (emit) {
            const ull A    = f2mul(Wu, Wu);
            const ull B    = f2mul(Wv, Wv);
            const ull amb  = F2SUB(A, B);
            const ull apb  = f2add(A, B);
            const ull namb = F2SUB(B, A);
            const ull napb = f2fma(apb, kNeg1, 0ull);
            const ull dmm  = F2SUB(Wuu, Wvv);
            const ull dpp  = f2add(Wuu, Wvv);
            const ull N1 = f2fma(kCh, amb, kC1);
            const ull D1 = f2fma(kCh, apb, kC1);
            const ull N2 = f2fma(kCvh, f2fma(k49, dmm, namb), kC2);
            const ull D2 = f2fma(kCvh, f2fma(k49, dpp, napb), kC2);
            const float2 N = f2up(f2mul(N1, N2));
            const float2 D = f2up(f2mul(D1, D2));
            // 2 cols -> one rational; pair rows -> 1 divide per 4 px
            const float n2r = fmaf(N.x, D.y, N.y * D.x);
            const float d2r = D.x * D.y;
            if (have) {
                acc += __fdividef(fmaf(pn, d2r, n2r * pd), pd * d2r);
                have = false;
            } else {
                pn = n2r; pd = d2r; have = true;
            }
        }
    };

    // ---- prologue: stage steps 0 and 1 ----
    stage(0, 0, WIN);
    stage(1, WIN, WIN);

    // step 0: rows 0..6, only row 6 emits; then prefetch step 2
    __pipeline_wait_prior(1);
    __syncthreads();
#pragma unroll
    for (int i = 0; i < WIN; i++) dorow(0, i, i == WIN - 1);
    __syncthreads();
    stage(0, 2 * WIN, WIN);

    // steps 1..6: full steps, all emit; prefetch step s+2
    for (int s = 1; s < 7; s++) {
        const int bi = s & 1;
        __pipeline_wait_prior(1);
        __syncthreads();
#pragma unroll
        for (int i = 0; i < WIN; i++) dorow(bi, i, true);
        __syncthreads();
        if (s + 2 <= 8)
            stage(bi, (s + 2) * WIN, (s + 2 == 8) ? (INROWS - 8 * WIN) : WIN);
    }

    // step 7: full, from buf1
    __pipeline_wait_prior(1);
    __syncthreads();
#pragma unroll
    for (int i = 0; i < WIN; i++) dorow(1, i, true);
    __syncthreads();

    // step 8: rows 56..59 (4 rows, ring slots 0..3), from buf0
    __pipeline_wait_prior(0);
    __syncthreads();
#pragma unroll
    for (int i = 0; i < 4; i++) dorow(0, i, true);

    if (have) acc += __fdividef(pn, pd);
    if (c + 1 >= OW) acc = 0.f;   // threads 189..191: pad garbage discarded

    // block reduction -> per-CTA partial
#pragma unroll
    for (int o = 16; o > 0; o >>= 1)
        acc += __shfl_xor_sync(0xffffffffu, acc, o);
    if ((t & 31) == 0) warpsum[t >> 5] = acc;
    __syncthreads();
    const int cta = b * NBANDS + band;
    if (t == 0) {
        float s = 0.f;
#pragma unroll
        for (int w = 0; w < NTHREADS / 32; w++) s += warpsum[w];
        g_part[cta] = s;
        __threadfence();
        unsigned int n = atomicAdd(&g_count, 1u);
        is_last = (n == NCTAS - 1) ? 1 : 0;
    }
    __syncthreads();

    // last CTA: deterministic final reduction (448 = 192 + 192 + 64)
    if (is_last) {
        __threadfence();
        double s = 0.0;
        s += (double)g_part[t];
        s += (double)g_part[t + NTHREADS];
        if (t < NCTAS - 2 * NTHREADS) s += (double)g_part[t + 2 * NTHREADS];
#pragma unroll
        for (int o = 16; o > 0; o >>= 1)
            s += __shfl_xor_sync(0xffffffffu, s, o);
        if ((t & 31) == 0) dsum[t >> 5] = s;
        __syncthreads();
        if (t == 0) {
            double tot = 0.0;
#pragma unroll
            for (int w = 0; w < NTHREADS / 32; w++) tot += dsum[w];
            out[0] = (float)(1.0 - tot / ((double)BATCH * OH * OW));
            g_count = 0;
        }
    }
}

extern "C" void kernel_launch(void* const* d_in, const int* in_sizes, int n_in,
                              void* d_out, int out_size)
{
    const float* X  = (const float*)d_in[0];
    const float* Y  = (const float*)d_in[1];
    const float* dr = (const float*)d_in[2];
    float* out = (float*)d_out;

    dim3 grid(NBANDS, BATCH);
    ssim_main_kernel<<<grid, NTHREADS>>>(X, Y, dr, out);
}

// round 12
// speedup vs baseline: 1.1646x; 1.1646x over previous
#include <cuda_runtime.h>
#include <cuda_pipeline_primitives.h>

// SSIM loss, fused single pass + fused finalize. B=64, H=W=384, WIN=7.
//
// R12 (= R11 retry; infra failure): base = R9 scalar cp.async double-buffered
// kernel, plus:
//  - NBANDS 7->9 (576 CTAs, 48 in-rows each): makespan 4x48=192 row-units
//    vs 4x60=240 -> better last-wave balance.
//  - Stats tracked as (Sx, Sy, Sxx+Syy, Sxy): no per-row u,v conversion
//    (N2/D2 only need the sum Sxx+Syy). Same 4-stat x 2-col x 7 ring.

#define BATCH    64
#define HH       384
#define WW       384
#define WIN      7
#define OH       378
#define OW       378
#define NBANDS   9
#define OROWS    42                     // output rows per band
#define INROWS   48                     // input rows per band
#define NTHREADS 192
#define ROWW     392
#define NF4      (WW / 4)
#define NCTAS    (NBANDS * BATCH)       // 576

__device__ float g_part[NCTAS];
__device__ unsigned int g_count;        // zero-init; last block resets to 0

__global__ __launch_bounds__(NTHREADS, 3) void ssim_main_kernel(
    const float* __restrict__ X, const float* __restrict__ Y,
    const float* __restrict__ data_range, float* __restrict__ out)
{
    __shared__ float xb[2][WIN][ROWW];
    __shared__ float yb[2][WIN][ROWW];
    __shared__ float warpsum[NTHREADS / 32];
    __shared__ double dsum[NTHREADS / 32];
    __shared__ int is_last;

    const int t    = threadIdx.x;
    const int band = blockIdx.x;
    const int b    = blockIdx.y;
    const int row0 = band * OROWS;
    const int c    = 2 * t;

    const float L     = data_range[b];
    const float C1s   = (0.49f * L) * (0.49f * L);   // C1 * 49^2
    const float C2s   = (1.47f * L) * (1.47f * L);   // C2 * 49^2
    const float covn  = 49.0f / 48.0f;
    const float covn2 = 2.0f * covn;

    const float* __restrict__ Xb = X + (size_t)b * HH * WW;
    const float* __restrict__ Yb = Y + (size_t)b * HH * WW;

    // rings: 4 stats x 2 cols x 7 (static idx via unroll)
    float rx0[WIN], rx1[WIN], ry0[WIN], ry1[WIN];
    float rp0[WIN], rp1[WIN], rq0[WIN], rq1[WIN];   // p = xx+yy, q = xy
#pragma unroll
    for (int i = 0; i < WIN; i++) {
        rx0[i]=0.f; rx1[i]=0.f; ry0[i]=0.f; ry1[i]=0.f;
        rp0[i]=0.f; rp1[i]=0.f; rq0[i]=0.f; rq1[i]=0.f;
    }
    float Wx0=0.f, Wx1=0.f, Wy0=0.f, Wy1=0.f;
    float Wp0=0.f, Wp1=0.f, Wq0=0.f, Wq1=0.f;
    float acc = 0.f;
    float pn = 0.f, pd = 1.f;
    bool  have = false;

    auto stage = [&](int bi, int r0, int nrows) {
        const float* __restrict__ Xr = Xb + (size_t)(row0 + r0) * WW;
        const float* __restrict__ Yr = Yb + (size_t)(row0 + r0) * WW;
        const int total = nrows * NF4;
        for (int e = t; e < total; e += NTHREADS) {
            const int rr = e / NF4;
            const int cc = (e - rr * NF4) * 4;
            __pipeline_memcpy_async(&xb[bi][rr][cc], Xr + rr * WW + cc, 16);
            __pipeline_memcpy_async(&yb[bi][rr][cc], Yr + rr * WW + cc, 16);
        }
        __pipeline_commit();
    };

    auto dorow = [&](int bi, int i, bool emit) {
        const float2 a0 = *(const float2*)&xb[bi][i][c];
        const float2 a1 = *(const float2*)&xb[bi][i][c + 2];
        const float2 a2 = *(const float2*)&xb[bi][i][c + 4];
        const float2 a3 = *(const float2*)&xb[bi][i][c + 6];
        const float2 b0 = *(const float2*)&yb[bi][i][c];
        const float2 b1 = *(const float2*)&yb[bi][i][c + 2];
        const float2 b2 = *(const float2*)&yb[bi][i][c + 4];
        const float2 b3 = *(const float2*)&yb[bi][i][c + 6];
        const float x0=a0.x, x1=a0.y, x2=a1.x, x3=a1.y, x4=a2.x, x5=a2.y, x6=a3.x, x7=a3.y;
        const float y0=b0.x, y1=b0.y, y2=b1.x, y3=b1.y, y4=b2.x, y5=b2.y, y6=b3.x, y7=b3.y;

        // linear 7-tap sums (col0 direct, col1 slide)
        const float sx0 = ((x0+x1)+(x2+x3)) + ((x4+x5)+x6);
        const float sx1 = (sx0 - x0) + x7;
        const float sy0 = ((y0+y1)+(y2+y3)) + ((y4+y5)+y6);
        const float sy1 = (sy0 - y0) + y7;

        // p = x^2+y^2 window sum
        float sp0 = x0*x0; sp0=fmaf(y0,y0,sp0);
        sp0=fmaf(x1,x1,sp0); sp0=fmaf(y1,y1,sp0);
        sp0=fmaf(x2,x2,sp0); sp0=fmaf(y2,y2,sp0);
        sp0=fmaf(x3,x3,sp0); sp0=fmaf(y3,y3,sp0);
        sp0=fmaf(x4,x4,sp0); sp0=fmaf(y4,y4,sp0);
        sp0=fmaf(x5,x5,sp0); sp0=fmaf(y5,y5,sp0);
        sp0=fmaf(x6,x6,sp0); sp0=fmaf(y6,y6,sp0);
        const float pa = fmaf(y0, y0, x0*x0);
        const float pb = fmaf(y7, y7, x7*x7);
        const float sp1 = (sp0 - pa) + pb;

        // q = x*y window sum
        float sq0 = x0*y0; sq0=fmaf(x1,y1,sq0); sq0=fmaf(x2,y2,sq0);
        sq0=fmaf(x3,y3,sq0); sq0=fmaf(x4,y4,sq0); sq0=fmaf(x5,y5,sq0); sq0=fmaf(x6,y6,sq0);
        const float sq1 = fmaf(x7, y7, fmaf(-x0, y0, sq0));

        // vertical running windows
        Wx0 += sx0 - rx0[i]; rx0[i] = sx0;
        Wx1 += sx1 - rx1[i]; rx1[i] = sx1;
        Wy0 += sy0 - ry0[i]; ry0[i] = sy0;
        Wy1 += sy1 - ry1[i]; ry1[i] = sy1;
        Wp0 += sp0 - rp0[i]; rp0[i] = sp0;
        Wp1 += sp1 - rp1[i]; rp1[i] = sp1;
        Wq0 += sq0 - rq0[i]; rq0[i] = sq0;
        Wq1 += sq1 - rq1[i]; rq1[i] = sq1;

        if (emit) {
            // scale-free SSIM (x 49^2)
            const float pxy0 = Wx0 * Wy0;
            const float pss0 = fmaf(Wx0, Wx0, Wy0 * Wy0);
            const float N1a = fmaf(2.0f, pxy0, C1s);
            const float D1a = pss0 + C1s;
            const float N2a = fmaf(covn2, fmaf(49.0f, Wq0, -pxy0), C2s);
            const float D2a = fmaf(covn,  fmaf(49.0f, Wp0, -pss0), C2s);
            const float Na = N1a * N2a;
            const float Da = D1a * D2a;
            const float pxy1 = Wx1 * Wy1;
            const float pss1 = fmaf(Wx1, Wx1, Wy1 * Wy1);
            const float N1b = fmaf(2.0f, pxy1, C1s);
            const float D1b = pss1 + C1s;
            const float N2b = fmaf(covn2, fmaf(49.0f, Wq1, -pxy1), C2s);
            const float D2b = fmaf(covn,  fmaf(49.0f, Wp1, -pss1), C2s);
            const float Nb = N1b * N2b;
            const float Db = D1b * D2b;
            // 2 cols -> one rational; pair rows -> 1 divide per 4 px
            const float n2r = fmaf(Na, Db, Nb * Da);
            const float d2r = Da * Db;
            if (have) {
                acc += __fdividef(fmaf(pn, d2r, n2r * pd), pd * d2r);
                have = false;
            } else {
                pn = n2r; pd = d2r; have = true;
            }
        }
    };

    // ---- prologue: stage steps 0 and 1 ----
    stage(0, 0, WIN);
    stage(1, WIN, WIN);

    // step 0: rows 0..6, only row 6 emits; then prefetch step 2
    __pipeline_wait_prior(1);
    __syncthreads();
#pragma unroll
    for (int i = 0; i < WIN; i++) dorow(0, i, i == WIN - 1);
    __syncthreads();
    stage(0, 2 * WIN, WIN);

    // steps 1..4: full steps, all emit; prefetch step s+2 (step 6 has 6 rows)
    for (int s = 1; s < 5; s++) {
        const int bi = s & 1;
        __pipeline_wait_prior(1);
        __syncthreads();
#pragma unroll
        for (int i = 0; i < WIN; i++) dorow(bi, i, true);
        __syncthreads();
        const int ns = s + 2;                      // 3..6
        stage(bi, ns * WIN, (ns == 6) ? (INROWS - 6 * WIN) : WIN);
    }

    // step 5: full, from buf1; nothing more to stage
    __pipeline_wait_prior(1);
    __syncthreads();
#pragma unroll
    for (int i = 0; i < WIN; i++) dorow(1, i, true);

    // step 6: rows 42..47 (6 rows, ring slots 0..5), from buf0
    __pipeline_wait_prior(0);
    __syncthreads();
#pragma unroll
    for (int i = 0; i < 6; i++) dorow(0, i, true);

    if (have) acc += __fdividef(pn, pd);
    if (c + 1 >= OW) acc = 0.f;   // threads 189..191: pad garbage discarded

    // block reduction -> per-CTA partial
#pragma unroll
    for (int o = 16; o > 0; o >>= 1)
        acc += __shfl_xor_sync(0xffffffffu, acc, o);
    if ((t & 31) == 0) warpsum[t >> 5] = acc;
    __syncthreads();
    const int cta = b * NBANDS + band;
    if (t == 0) {
        float s = 0.f;
#pragma unroll
        for (int w = 0; w < NTHREADS / 32; w++) s += warpsum[w];
        g_part[cta] = s;
        __threadfence();
        unsigned int n = atomicAdd(&g_count, 1u);
        is_last = (n == NCTAS - 1) ? 1 : 0;
    }
    __syncthreads();

    // last CTA: deterministic final reduction (576 = 3 * 192)
    if (is_last) {
        __threadfence();
        double s = 0.0;
        s += (double)g_part[t];
        s += (double)g_part[t + NTHREADS];
        s += (double)g_part[t + 2 * NTHREADS];
#pragma unroll
        for (int o = 16; o > 0; o >>= 1)
            s += __shfl_xor_sync(0xffffffffu, s, o);
        if ((t & 31) == 0) dsum[t >> 5] = s;
        __syncthreads();
        if (t == 0) {
            double tot = 0.0;
#pragma unroll
            for (int w = 0; w < NTHREADS / 32; w++) tot += dsum[w];
            out[0] = (float)(1.0 - tot / ((double)BATCH * OH * OW));
            g_count = 0;   // reset for next graph replay
        }
    }
}

extern "C" void kernel_launch(void* const* d_in, const int* in_sizes, int n_in,
                              void* d_out, int out_size)
{
    const float* X  = (const float*)d_in[0];
    const float* Y  = (const float*)d_in[1];
    const float* dr = (const float*)d_in[2];
    float* out = (float*)d_out;

    dim3 grid(NBANDS, BATCH);
    ssim_main_kernel<<<grid, NTHREADS>>>(X, Y, dr, out);
}

// round 13
// speedup vs baseline: 1.1730x; 1.0072x over previous
#include <cuda_runtime.h>
#include <cuda_pipeline_primitives.h>

// SSIM loss, fused single pass + fused finalize. B=64, H=W=384, WIN=7.
//
// R13: ILP fix on the R12 base. The 7/14-term tap reductions are restructured
// into parallel partial chains (sp: 2x7 fmaf chains, depth 56->32; sq: 4+3
// split, depth 28->20), cutting the per-row critical path ~120 -> ~70 cyc so
// ~3.7 warps/SMSP can cover it. Everything else (cp.async double buffering,
// NBANDS=9, 4-stat ring, every-row emit with divide pairing, fused last-block
// finalize) unchanged from R12.

#define BATCH    64
#define HH       384
#define WW       384
#define WIN      7
#define OH       378
#define OW       378
#define NBANDS   9
#define OROWS    42                     // output rows per band
#define INROWS   48                     // input rows per band
#define NTHREADS 192
#define ROWW     392
#define NF4      (WW / 4)
#define NCTAS    (NBANDS * BATCH)       // 576

__device__ float g_part[NCTAS];
__device__ unsigned int g_count;        // zero-init; last block resets to 0

__global__ __launch_bounds__(NTHREADS, 3) void ssim_main_kernel(
    const float* __restrict__ X, const float* __restrict__ Y,
    const float* __restrict__ data_range, float* __restrict__ out)
{
    __shared__ float xb[2][WIN][ROWW];
    __shared__ float yb[2][WIN][ROWW];
    __shared__ float warpsum[NTHREADS / 32];
    __shared__ double dsum[NTHREADS / 32];
    __shared__ int is_last;

    const int t    = threadIdx.x;
    const int band = blockIdx.x;
    const int b    = blockIdx.y;
    const int row0 = band * OROWS;
    const int c    = 2 * t;

    const float L     = data_range[b];
    const float C1s   = (0.49f * L) * (0.49f * L);   // C1 * 49^2
    const float C2s   = (1.47f * L) * (1.47f * L);   // C2 * 49^2
    const float covn  = 49.0f / 48.0f;
    const float covn2 = 2.0f * covn;

    const float* __restrict__ Xb = X + (size_t)b * HH * WW;
    const float* __restrict__ Yb = Y + (size_t)b * HH * WW;

    // rings: 4 stats x 2 cols x 7 (static idx via unroll)
    float rx0[WIN], rx1[WIN], ry0[WIN], ry1[WIN];
    float rp0[WIN], rp1[WIN], rq0[WIN], rq1[WIN];   // p = xx+yy, q = xy
#pragma unroll
    for (int i = 0; i < WIN; i++) {
        rx0[i]=0.f; rx1[i]=0.f; ry0[i]=0.f; ry1[i]=0.f;
        rp0[i]=0.f; rp1[i]=0.f; rq0[i]=0.f; rq1[i]=0.f;
    }
    float Wx0=0.f, Wx1=0.f, Wy0=0.f, Wy1=0.f;
    float Wp0=0.f, Wp1=0.f, Wq0=0.f, Wq1=0.f;
    float acc = 0.f;
    float pn = 0.f, pd = 1.f;
    bool  have = false;

    auto stage = [&](int bi, int r0, int nrows) {
        const float* __restrict__ Xr = Xb + (size_t)(row0 + r0) * WW;
        const float* __restrict__ Yr = Yb + (size_t)(row0 + r0) * WW;
        const int total = nrows * NF4;
        for (int e = t; e < total; e += NTHREADS) {
            const int rr = e / NF4;
            const int cc = (e - rr * NF4) * 4;
            __pipeline_memcpy_async(&xb[bi][rr][cc], Xr + rr * WW + cc, 16);
            __pipeline_memcpy_async(&yb[bi][rr][cc], Yr + rr * WW + cc, 16);
        }
        __pipeline_commit();
    };

    auto dorow = [&](int bi, int i, bool emit) {
        const float2 a0 = *(const float2*)&xb[bi][i][c];
        const float2 a1 = *(const float2*)&xb[bi][i][c + 2];
        const float2 a2 = *(const float2*)&xb[bi][i][c + 4];
        const float2 a3 = *(const float2*)&xb[bi][i][c + 6];
        const float2 b0 = *(const float2*)&yb[bi][i][c];
        const float2 b1 = *(const float2*)&yb[bi][i][c + 2];
        const float2 b2 = *(const float2*)&yb[bi][i][c + 4];
        const float2 b3 = *(const float2*)&yb[bi][i][c + 6];
        const float x0=a0.x, x1=a0.y, x2=a1.x, x3=a1.y, x4=a2.x, x5=a2.y, x6=a3.x, x7=a3.y;
        const float y0=b0.x, y1=b0.y, y2=b1.x, y3=b1.y, y4=b2.x, y5=b2.y, y6=b3.x, y7=b3.y;

        // linear 7-tap sums: pairwise tree (depth 3 fma-lats)
        const float tx01 = x0 + x1, tx23 = x2 + x3, tx45 = x4 + x5;
        const float sx0 = (tx01 + tx23) + (tx45 + x6);
        const float sx1 = (sx0 - x0) + x7;
        const float ty01 = y0 + y1, ty23 = y2 + y3, ty45 = y4 + y5;
        const float sy0 = (ty01 + ty23) + (ty45 + y6);
        const float sy1 = (sy0 - y0) + y7;

        // p = x^2+y^2 window sum: two parallel 7-op fmaf chains (depth 32 vs 56)
        float pA = x0 * x0;
        pA = fmaf(y0, y0, pA); pA = fmaf(x1, x1, pA); pA = fmaf(y1, y1, pA);
        pA = fmaf(x2, x2, pA); pA = fmaf(y2, y2, pA); pA = fmaf(x3, x3, pA);
        float pB = y3 * y3;
        pB = fmaf(x4, x4, pB); pB = fmaf(y4, y4, pB); pB = fmaf(x5, x5, pB);
        pB = fmaf(y5, y5, pB); pB = fmaf(x6, x6, pB); pB = fmaf(y6, y6, pB);
        const float sp0 = pA + pB;
        const float p0 = fmaf(y0, y0, x0 * x0);
        const float p7 = fmaf(y7, y7, x7 * x7);
        const float sp1 = (sp0 - p0) + p7;

        // q = x*y window sum: 4-term + 3-term parallel chains (depth 20 vs 28)
        float qA = x0 * y0;
        qA = fmaf(x1, y1, qA); qA = fmaf(x2, y2, qA); qA = fmaf(x3, y3, qA);
        float qB = x4 * y4;
        qB = fmaf(x5, y5, qB); qB = fmaf(x6, y6, qB);
        const float sq0 = qA + qB;
        const float sq1 = fmaf(x7, y7, sq0 - x0 * y0);

        // vertical running windows
        Wx0 += sx0 - rx0[i]; rx0[i] = sx0;
        Wx1 += sx1 - rx1[i]; rx1[i] = sx1;
        Wy0 += sy0 - ry0[i]; ry0[i] = sy0;
        Wy1 += sy1 - ry1[i]; ry1[i] = sy1;
        Wp0 += sp0 - rp0[i]; rp0[i] = sp0;
        Wp1 += sp1 - rp1[i]; rp1[i] = sp1;
        Wq0 += sq0 - rq0[i]; rq0[i] = sq0;
        Wq1 += sq1 - rq1[i]; rq1[i] = sq1;

        if (emit) {
            // scale-free SSIM (x 49^2)
            const float pxy0 = Wx0 * Wy0;
            const float pss0 = fmaf(Wx0, Wx0, Wy0 * Wy0);
            const float N1a = fmaf(2.0f, pxy0, C1s);
            const float D1a = pss0 + C1s;
            const float N2a = fmaf(covn2, fmaf(49.0f, Wq0, -pxy0), C2s);
            const float D2a = fmaf(covn,  fmaf(49.0f, Wp0, -pss0), C2s);
            const float Na = N1a * N2a;
            const float Da = D1a * D2a;
            const float pxy1 = Wx1 * Wy1;
            const float pss1 = fmaf(Wx1, Wx1, Wy1 * Wy1);
            const float N1b = fmaf(2.0f, pxy1, C1s);
            const float D1b = pss1 + C1s;
            const float N2b = fmaf(covn2, fmaf(49.0f, Wq1, -pxy1), C2s);
            const float D2b = fmaf(covn,  fmaf(49.0f, Wp1, -pss1), C2s);
            const float Nb = N1b * N2b;
            const float Db = D1b * D2b;
            // 2 cols -> one rational; pair rows -> 1 divide per 4 px
            const float n2r = fmaf(Na, Db, Nb * Da);
            const float d2r = Da * Db;
            if (have) {
                acc += __fdividef(fmaf(pn, d2r, n2r * pd), pd * d2r);
                have = false;
            } else {
                pn = n2r; pd = d2r; have = true;
            }
        }
    };

    // ---- prologue: stage steps 0 and 1 ----
    stage(0, 0, WIN);
    stage(1, WIN, WIN);

    // step 0: rows 0..6, only row 6 emits; then prefetch step 2
    __pipeline_wait_prior(1);
    __syncthreads();
#pragma unroll
    for (int i = 0; i < WIN; i++) dorow(0, i, i == WIN - 1);
    __syncthreads();
    stage(0, 2 * WIN, WIN);

    // steps 1..4: full steps, all emit; prefetch step s+2 (step 6 has 6 rows)
    for (int s = 1; s < 5; s++) {
        const int bi = s & 1;
        __pipeline_wait_prior(1);
        __syncthreads();
#pragma unroll
        for (int i = 0; i < WIN; i++) dorow(bi, i, true);
        __syncthreads();
        const int ns = s + 2;                      // 3..6
        stage(bi, ns * WIN, (ns == 6) ? (INROWS - 6 * WIN) : WIN);
    }

    // step 5: full, from buf1; nothing more to stage
    __pipeline_wait_prior(1);
    __syncthreads();
#pragma unroll
    for (int i = 0; i < WIN; i++) dorow(1, i, true);

    // step 6: rows 42..47 (6 rows, ring slots 0..5), from buf0
    __pipeline_wait_prior(0);
    __syncthreads();
#pragma unroll
    for (int i = 0; i < 6; i++) dorow(0, i, true);

    if (have) acc += __fdividef(pn, pd);
    if (c + 1 >= OW) acc = 0.f;   // threads 189..191: pad garbage discarded

    // block reduction -> per-CTA partial
#pragma unroll
    for (int o = 16; o > 0; o >>= 1)
        acc += __shfl_xor_sync(0xffffffffu, acc, o);
    if ((t & 31) == 0) warpsum[t >> 5] = acc;
    __syncthreads();
    const int cta = b * NBANDS + band;
    if (t == 0) {
        float s = 0.f;
#pragma unroll
        for (int w = 0; w < NTHREADS / 32; w++) s += warpsum[w];
        g_part[cta] = s;
        __threadfence();
        unsigned int n = atomicAdd(&g_count, 1u);
        is_last = (n == NCTAS - 1) ? 1 : 0;
    }
    __syncthreads();

    // last CTA: deterministic final reduction (576 = 3 * 192)
    if (is_last) {
        __threadfence();
        double s = 0.0;
        s += (double)g_part[t];
        s += (double)g_part[t + NTHREADS];
        s += (double)g_part[t + 2 * NTHREADS];
#pragma unroll
        for (int o = 16; o > 0; o >>= 1)
            s += __shfl_xor_sync(0xffffffffu, s, o);
        if ((t & 31) == 0) dsum[t >> 5] = s;
        __syncthreads();
        if (t == 0) {
            double tot = 0.0;
#pragma unroll
            for (int w = 0; w < NTHREADS / 32; w++) tot += dsum[w];
            out[0] = (float)(1.0 - tot / ((double)BATCH * OH * OW));
            g_count = 0;   // reset for next graph replay
        }
    }
}

extern "C" void kernel_launch(void* const* d_in, const int* in_sizes, int n_in,
                              void* d_out, int out_size)
{
    const float* X  = (const float*)d_in[0];
    const float* Y  = (const float*)d_in[1];
    const float* dr = (const float*)d_in[2];
    float* out = (float*)d_out;

    dim3 grid(NBANDS, BATCH);
    ssim_main_kernel<<<grid, NTHREADS>>>(X, Y, dr, out);
}